// round 12
// baseline (speedup 1.0000x reference)
#include <cuda_runtime.h>

#define NN   50000
#define EE   500000
#define EMBD 50
#define EMBP 52
#define C1   256
#define C2   50
#define ED   28
#define EB   64

static __device__ float  g_xl[(size_t)NN * C1];
static __device__ float  g_xr[(size_t)NN * C1];
static __device__ float  g_h1[(size_t)NN * C1];
static __device__ float  g_logit[(size_t)EE * 4];
static __device__ float  g_max[(size_t)5 * NN];
static __device__ int    g_off[NN + 1];
static __device__ int    g_cur[NN];
static __device__ int    g_eid[EE];
static __device__ int    g_esrc[EE];
static __device__ int    g_edst[EE];
static __device__ float  g_o2[(size_t)NN * C2];
static __device__ double g_red[4];

__device__ __forceinline__ float lrelu(float v) { return v > 0.f ? v : 0.2f * v; }

__device__ __forceinline__ void atomicMaxF(float* a, float v) {
    if (!(__float_as_uint(v) >> 31)) atomicMax((int*)a, __float_as_int(v));
    else                             atomicMin((unsigned int*)a, __float_as_uint(v));
}

__device__ __forceinline__ unsigned int cvt_tf32(float v) {
    unsigned int t;
    asm("cvt.rna.tf32.f32 %0, %1;" : "=r"(t) : "f"(v));
    return t;
}

// ---- packed f32x2 helpers (node kernels) ----
__device__ __forceinline__ unsigned long long fma2(unsigned long long a,
                                                   unsigned long long b,
                                                   unsigned long long c) {
    unsigned long long d;
    asm("fma.rn.f32x2 %0, %1, %2, %3;" : "=l"(d) : "l"(a), "l"(b), "l"(c));
    return d;
}
__device__ __forceinline__ unsigned long long pack2(float x, float y) {
    unsigned long long d;
    asm("mov.b64 %0, {%1, %2};" : "=l"(d) : "r"(__float_as_int(x)), "r"(__float_as_int(y)));
    return d;
}
__device__ __forceinline__ float2 unpack2(unsigned long long v) {
    int lo, hi;
    asm("mov.b64 {%0, %1}, %2;" : "=r"(lo), "=r"(hi) : "l"(v));
    return make_float2(__int_as_float(lo), __int_as_float(hi));
}

__global__ void k_init() {
    int i = blockIdx.x * blockDim.x + threadIdx.x;
    if (i < 5 * NN) g_max[i] = __int_as_float(0xFF800000);
    if (i < NN) g_cur[i] = 0;
    if (i < 4)  g_red[i] = 0.0;
}

__global__ void k_deg(const int* __restrict__ ei) {
    int e = blockIdx.x * blockDim.x + threadIdx.x;
    if (e < EE) atomicAdd(&g_cur[ei[EE + e]], 1);
}

// coalesced single-block scan through 200KB smem
__global__ void k_scan() {
    extern __shared__ int si[];
    int t = threadIdx.x;
    for (int i = t; i < NN; i += 1024) si[i] = g_cur[i];
    __syncthreads();
    const int CH = (NN + 1023) / 1024;
    int lane = t & 31, w = t >> 5;
    int beg = t * CH;
    int end = beg + CH; if (end > NN) end = NN;
    int s = 0;
    for (int i = beg; i < end; i++) s += si[i];
    int incl = s;
#pragma unroll
    for (int off = 1; off < 32; off <<= 1) {
        int y = __shfl_up_sync(0xffffffffu, incl, off);
        if (lane >= off) incl += y;
    }
    __shared__ int ws[32];
    if (lane == 31) ws[w] = incl;
    __syncthreads();
    if (w == 0) {
        int v = ws[lane];
#pragma unroll
        for (int off = 1; off < 32; off <<= 1) {
            int y = __shfl_up_sync(0xffffffffu, v, off);
            if (lane >= off) v += y;
        }
        ws[lane] = v;
    }
    __syncthreads();
    int run = incl - s + (w > 0 ? ws[w - 1] : 0);
    for (int i = beg; i < end; i++) {
        int v = si[i];
        si[i] = run;
        run += v;
    }
    __syncthreads();
    for (int i = t; i < NN; i += 1024) {
        int v = si[i];
        g_off[i] = v;
        g_cur[i] = v;
    }
    if (t == 0) g_off[NN] = ws[31];
}

__global__ void k_fill(const int* __restrict__ ei) {
    int e = blockIdx.x * blockDim.x + threadIdx.x;
    if (e < EE) {
        int d = ei[EE + e];
        int pos = atomicAdd(&g_cur[d], 1);
        g_eid[pos]  = e;
        g_esrc[pos] = ei[e];
        g_edst[pos] = d;
    }
}

// node transform L1 (xl or xr per launch): f32x2 with smem-duplicated h splats
__global__ __launch_bounds__(256) void k_node1(const int* __restrict__ x,
                                               const float* __restrict__ emb,
                                               const float* __restrict__ W,
                                               const float* __restrict__ bvec,
                                               int sel) {
    extern __shared__ float sm[];
    float* s_w  = sm;
    float* s_h2 = sm + EMBP * C1;
    __shared__ int xs[32];
    int t = threadIdx.x;
    int nb = blockIdx.x * 32;
    if (t < 32) xs[t] = (nb + t < NN) ? x[nb + t] : 0;
    for (int i = t; i < EMBD * C1 / 4; i += 256)
        ((float4*)s_w)[i] = ((const float4*)W)[i];
    for (int i = t; i < (EMBP - EMBD) * C1 / 4; i += 256)
        ((float4*)s_w)[EMBD * C1 / 4 + i] = make_float4(0.f, 0.f, 0.f, 0.f);
    __syncthreads();
    for (int i = t; i < 32 * EMBP; i += 256) {
        int n = i / EMBP, k = i % EMBP;
        float v = (k < EMBD) ? emb[(size_t)xs[n] * EMBD + k] : 0.f;
        s_h2[i * 2] = v; s_h2[i * 2 + 1] = v;
    }
    __syncthreads();
    int cg = t & 63, g = t >> 6;
    int c0 = cg * 4;
    float4 bv = *(const float4*)&bvec[c0];
    ulonglong2 acc[8];
#pragma unroll
    for (int j = 0; j < 8; j++) {
        acc[j].x = pack2(bv.x, bv.y);
        acc[j].y = pack2(bv.z, bv.w);
    }
#pragma unroll 4
    for (int k = 0; k < EMBP; k++) {
        ulonglong2 w = *(const ulonglong2*)&s_w[k * C1 + c0];
#pragma unroll
        for (int j = 0; j < 8; j++) {
            unsigned long long h2 =
                *(const unsigned long long*)&s_h2[((g * 8 + j) * EMBP + k) * 2];
            acc[j].x = fma2(h2, w.x, acc[j].x);
            acc[j].y = fma2(h2, w.y, acc[j].y);
        }
    }
    float* dst = sel ? g_xr : g_xl;
#pragma unroll
    for (int j = 0; j < 8; j++) {
        int n = nb + g * 8 + j;
        if (n < NN) {
            float2 lo = unpack2(acc[j].x), hi = unpack2(acc[j].y);
            *(float4*)&dst[(size_t)n * C1 + c0] = make_float4(lo.x, lo.y, hi.x, hi.y);
        }
    }
}

// edge logits L1, CSR order: tf32 mma.sync for xe GEMM, fp32 epilogue
// block = 64 edges, 128 threads (4 warps x 16 edge rows)
__global__ __launch_bounds__(128) void k_edge1(const float* __restrict__ ea,
                                               const float* __restrict__ We,
                                               const float* __restrict__ att) {
    extern __shared__ float sm[];
    float* s_web = sm;                        // 4*32*32*2 = 8192 floats (b-frag order)
    float* s_eaf = sm + 8192;                 // 4*4*32*4  = 2048 floats (a-frag order)
    float* s_att = sm + 10240;                // 256
    float* s_m   = sm + 10496;                // 64 rows x 264 stride = 16896
    __shared__ int s_src[EB], s_dst[EB];
    __shared__ int s_eid[EB];
    int t = threadIdx.x;
    int eb = blockIdx.x * EB;
    if (t < EB) {
        int idx = eb + t;
        bool ok = idx < EE;
        s_src[t] = ok ? g_esrc[idx] : 0;
        s_dst[t] = ok ? g_edst[idx] : 0;
        s_eid[t] = ok ? g_eid[idx] : 0;
    }
    __syncthreads();
    // stage We into b-fragment layout (tf32)
    for (int i = t; i < 32 * C1; i += 128) {
        int k = i >> 8, n = i & 255;
        float v = (k < ED) ? We[k * C1 + n] : 0.f;
        unsigned int tv = cvt_tf32(v);
        int kt = k >> 3, kk = k & 7, nt = n >> 3, nn = n & 7;
        int lane = nn * 4 + (kk & 3), slot = kk >> 2;
        ((unsigned int*)s_web)[((kt * 32 + nt) * 32 + lane) * 2 + slot] = tv;
    }
    // stage ea into a-fragment layout (tf32)
    for (int i = t; i < EB * 32; i += 128) {
        int e = i >> 5, k = i & 31;
        float v = (k < ED && eb + e < EE) ? ea[(size_t)s_eid[e] * ED + k] : 0.f;
        unsigned int tv = cvt_tf32(v);
        int w = e >> 4, r = e & 15;
        int kt = k >> 3, kk = k & 7;
        int lane = (r & 7) * 4 + (kk & 3);
        int slot = (r >> 3) | ((kk >> 2) << 1);
        ((unsigned int*)s_eaf)[((w * 4 + kt) * 32 + lane) * 4 + slot] = tv;
    }
    for (int i = t; i < C1; i += 128) s_att[i] = att[i];
    // stage xl[src]+xr[dst] (fp32, padded stride 264)
    for (int i = t; i < EB * 64; i += 128) {
        int e = i >> 6, c4 = (i & 63) * 4;
        float4 a = *(const float4*)&g_xl[(size_t)s_src[e] * C1 + c4];
        float4 b = *(const float4*)&g_xr[(size_t)s_dst[e] * C1 + c4];
        a.x += b.x; a.y += b.y; a.z += b.z; a.w += b.w;
        *(float4*)&s_m[e * 264 + c4] = a;
    }
    __syncthreads();
    int w = t >> 5, l = t & 31;
    int r = l >> 2, q = l & 3;
    int e_lo = w * 16 + r, e_hi = e_lo + 8;
    for (int h = 0; h < 4; h++) {           // 64-col chunk == head
        float c[8][4];
#pragma unroll
        for (int nt = 0; nt < 8; nt++) {
            c[nt][0] = 0.f; c[nt][1] = 0.f; c[nt][2] = 0.f; c[nt][3] = 0.f;
        }
#pragma unroll
        for (int kt = 0; kt < 4; kt++) {
            uint4 av = *(const uint4*)&((unsigned int*)s_eaf)[((w * 4 + kt) * 32 + l) * 4];
#pragma unroll
            for (int nt = 0; nt < 8; nt++) {
                int ntg = h * 8 + nt;
                uint2 bv = *(const uint2*)&((unsigned int*)s_web)[((kt * 32 + ntg) * 32 + l) * 2];
                asm volatile(
                    "mma.sync.aligned.m16n8k8.row.col.f32.tf32.tf32.f32 "
                    "{%0,%1,%2,%3}, {%4,%5,%6,%7}, {%8,%9}, {%0,%1,%2,%3};"
                    : "+f"(c[nt][0]), "+f"(c[nt][1]), "+f"(c[nt][2]), "+f"(c[nt][3])
                    : "r"(av.x), "r"(av.y), "r"(av.z), "r"(av.w),
                      "r"(bv.x), "r"(bv.y));
            }
        }
        float plo = 0.f, phi = 0.f;
#pragma unroll
        for (int nt = 0; nt < 8; nt++) {
            int col = h * 64 + nt * 8 + 2 * q;
            float2 m0 = *(const float2*)&s_m[e_lo * 264 + col];
            float2 m1 = *(const float2*)&s_m[e_hi * 264 + col];
            float2 at = *(const float2*)&s_att[col];
            plo += at.x * lrelu(c[nt][0] + m0.x) + at.y * lrelu(c[nt][1] + m0.y);
            phi += at.x * lrelu(c[nt][2] + m1.x) + at.y * lrelu(c[nt][3] + m1.y);
        }
        plo += __shfl_xor_sync(0xffffffffu, plo, 1);
        plo += __shfl_xor_sync(0xffffffffu, plo, 2);
        phi += __shfl_xor_sync(0xffffffffu, phi, 1);
        phi += __shfl_xor_sync(0xffffffffu, phi, 2);
        if (q == 0) {
            int ge = eb + e_lo;
            if (ge < EE) {
                g_logit[(size_t)ge * 4 + h] = plo;
                atomicMaxF(&g_max[s_dst[e_lo] * 4 + h], plo);
            }
            ge = eb + e_hi;
            if (ge < EE) {
                g_logit[(size_t)ge * 4 + h] = phi;
                atomicMaxF(&g_max[s_dst[e_hi] * 4 + h], phi);
            }
        }
    }
}

// aggregation L1 with fused softmax + fused LN stats
__global__ __launch_bounds__(256) void k_agg1(const float* __restrict__ bias) {
    int t = threadIdx.x;
    int n = blockIdx.x * 4 + (t >> 6);
    int t64 = t & 63;
    int lane = t & 31;
    int c0 = t64 * 4;
    int h  = t64 >> 4;
    int s = g_off[n], en = g_off[n + 1];
    float mx = g_max[n * 4 + h];
    float den = 0.f;
    float4 acc = make_float4(0.f, 0.f, 0.f, 0.f);
    for (int p = s; p < en; p++) {
        float ex = 0.f;
        if ((lane & 15) == 0) ex = expf(g_logit[(size_t)p * 4 + h] - mx);
        ex = __shfl_sync(0xffffffffu, ex, lane & 16);
        den += ex;
        int src = g_esrc[p];
        float4 v = *(const float4*)&g_xl[(size_t)src * C1 + c0];
        acc.x += ex * v.x; acc.y += ex * v.y;
        acc.z += ex * v.z; acc.w += ex * v.w;
    }
    float inv = 1.f / (den + 1e-16f);
    float4 bv = *(const float4*)&bias[c0];
    float4 o;
    o.x = acc.x * inv + bv.x; o.y = acc.y * inv + bv.y;
    o.z = acc.z * inv + bv.z; o.w = acc.w * inv + bv.w;
    *(float4*)&g_h1[(size_t)n * C1 + c0] = o;
    float sv = o.x + o.y + o.z + o.w;
    float qv = o.x * o.x + o.y * o.y + o.z * o.z + o.w * o.w;
#pragma unroll
    for (int off = 16; off; off >>= 1) {
        sv += __shfl_down_sync(0xffffffffu, sv, off);
        qv += __shfl_down_sync(0xffffffffu, qv, off);
    }
    __shared__ double sh[8], qh[8];
    int w = t >> 5;
    if (lane == 0) { sh[w] = (double)sv; qh[w] = (double)qv; }
    __syncthreads();
    if (t == 0) {
        double S = 0.0, Q = 0.0;
        for (int i = 0; i < 8; i++) { S += sh[i]; Q += qh[i]; }
        atomicAdd(&g_red[0], S); atomicAdd(&g_red[1], Q);
    }
}

// node transform L2: fused LN1+ReLU, duplicated-h smem, f32x2
__global__ __launch_bounds__(256) void k_node2(const float* __restrict__ Wl,
                                               const float* __restrict__ bl,
                                               const float* __restrict__ Wr,
                                               const float* __restrict__ br,
                                               const float* __restrict__ lnw,
                                               const float* __restrict__ lnb) {
    __shared__ float hs2[16 * C1 * 2];
    __shared__ float s_lnw[C1], s_lnb[C1];
    __shared__ float s_mf[2];
    int t = threadIdx.x;
    int nb = blockIdx.x * 16;
    if (t < C1) { s_lnw[t] = lnw[t]; s_lnb[t] = lnb[t]; }
    if (t == 0) {
        double M = (double)NN * C1;
        double mean = g_red[0] / M;
        double var  = g_red[1] / M - mean * mean;
        s_mf[0] = (float)mean;
        s_mf[1] = 1.f / ((float)sqrt(var > 0.0 ? var : 0.0) + 1e-5f);
    }
    __syncthreads();
    float mean = s_mf[0], f = s_mf[1];
    for (int i = t; i < 16 * C1 / 4; i += 256) {
        float4 v = *(const float4*)&g_h1[(size_t)nb * C1 + (size_t)i * 4];
        int k = (i & 63) * 4;
        float4 w4 = *(const float4*)&s_lnw[k];
        float4 b4 = *(const float4*)&s_lnb[k];
        v.x = (v.x - mean) * f * w4.x + b4.x; v.x = v.x > 0.f ? v.x : 0.f;
        v.y = (v.y - mean) * f * w4.y + b4.y; v.y = v.y > 0.f ? v.y : 0.f;
        v.z = (v.z - mean) * f * w4.z + b4.z; v.z = v.z > 0.f ? v.z : 0.f;
        v.w = (v.w - mean) * f * w4.w + b4.w; v.w = v.w > 0.f ? v.w : 0.f;
        *(float4*)&hs2[i * 8]     = make_float4(v.x, v.x, v.y, v.y);
        *(float4*)&hs2[i * 8 + 4] = make_float4(v.z, v.z, v.w, v.w);
    }
    __syncthreads();
    int cp = t & 31;
    int c2 = cp * 2;
    int grp = t >> 5;
    int n0 = grp * 2, n1 = grp * 2 + 1;
    bool act = (c2 + 1) < C2;
    unsigned long long blv = 0, brv = 0;
    if (act) {
        blv = pack2(bl[c2], bl[c2 + 1]);
        brv = pack2(br[c2], br[c2 + 1]);
    }
    unsigned long long al0 = blv, al1 = blv, ar0 = brv, ar1 = brv;
#pragma unroll 4
    for (int k = 0; k < C1; k++) {
        unsigned long long wl = 0, wr = 0;
        if (act) {
            wl = *(const unsigned long long*)&Wl[k * C2 + c2];
            wr = *(const unsigned long long*)&Wr[k * C2 + c2];
        }
        unsigned long long h0 = *(const unsigned long long*)&hs2[(n0 * C1 + k) * 2];
        unsigned long long h1 = *(const unsigned long long*)&hs2[(n1 * C1 + k) * 2];
        al0 = fma2(h0, wl, al0);
        al1 = fma2(h1, wl, al1);
        ar0 = fma2(h0, wr, ar0);
        ar1 = fma2(h1, wr, ar1);
    }
    if (act) {
        float2 v;
        v = unpack2(al0); *(float2*)&g_xl[(size_t)(nb + n0) * C2 + c2] = v;
        v = unpack2(al1); *(float2*)&g_xl[(size_t)(nb + n1) * C2 + c2] = v;
        v = unpack2(ar0); *(float2*)&g_xr[(size_t)(nb + n0) * C2 + c2] = v;
        v = unpack2(ar1); *(float2*)&g_xr[(size_t)(nb + n1) * C2 + c2] = v;
    }
}

// edge logits L2 in CSR order, warp per edge
__global__ __launch_bounds__(256) void k_edge2(const float* __restrict__ ea,
                                               const float* __restrict__ We,
                                               const float* __restrict__ att) {
    int lane = threadIdx.x & 31;
    int gw = (blockIdx.x * blockDim.x + threadIdx.x) >> 5;
    int nw = (gridDim.x * blockDim.x) >> 5;
    int c0 = lane * 2;
    bool act = c0 < C2;
    float2 w[ED];
#pragma unroll
    for (int k = 0; k < ED; k++)
        w[k] = act ? *(const float2*)&We[k * C2 + c0] : make_float2(0.f, 0.f);
    float2 a2 = act ? *(const float2*)&att[c0] : make_float2(0.f, 0.f);
    for (int p = gw; p < EE; p += nw) {
        int src = g_esrc[p], dst = g_edst[p], e = g_eid[p];
        float eav = (lane < ED) ? ea[(size_t)e * ED + lane] : 0.f;
        float mx = 0.f, my = 0.f;
        if (act) {
            float2 u = *(const float2*)&g_xl[(size_t)src * C2 + c0];
            float2 v = *(const float2*)&g_xr[(size_t)dst * C2 + c0];
            mx = u.x + v.x; my = u.y + v.y;
        }
#pragma unroll
        for (int k = 0; k < ED; k++) {
            float a = __shfl_sync(0xffffffffu, eav, k);
            mx += a * w[k].x; my += a * w[k].y;
        }
        float pt = lrelu(mx) * a2.x + lrelu(my) * a2.y;
#pragma unroll
        for (int off = 16; off; off >>= 1) pt += __shfl_down_sync(0xffffffffu, pt, off);
        if (lane == 0) {
            g_logit[p] = pt;
            atomicMaxF(&g_max[4 * NN + dst], pt);
        }
    }
}

// aggregation L2 with fused softmax + fused LN stats
__global__ __launch_bounds__(256) void k_agg2(const float* __restrict__ bias) {
    int t = threadIdx.x;
    int n = blockIdx.x * 4 + (t >> 6);
    int t64 = t & 63;
    int lane = t & 31;
    int s = g_off[n], en = g_off[n + 1];
    bool act = t64 < C2;
    float mx = g_max[4 * NN + n];
    float den = 0.f, acc = 0.f;
    for (int p = s; p < en; p++) {
        float ex = 0.f;
        if (lane == 0) ex = expf(g_logit[p] - mx);
        ex = __shfl_sync(0xffffffffu, ex, 0);
        den += ex;
        int src = g_esrc[p];
        if (act) acc += ex * g_xl[(size_t)src * C2 + t64];
    }
    float o = 0.f;
    if (act) {
        o = acc / (den + 1e-16f) + bias[t64];
        g_o2[(size_t)n * C2 + t64] = o;
    }
    float sv = o, qv = o * o;
#pragma unroll
    for (int off = 16; off; off >>= 1) {
        sv += __shfl_down_sync(0xffffffffu, sv, off);
        qv += __shfl_down_sync(0xffffffffu, qv, off);
    }
    __shared__ double sh[8], qh[8];
    int w = t >> 5;
    if (lane == 0) { sh[w] = (double)sv; qh[w] = (double)qv; }
    __syncthreads();
    if (t == 0) {
        double S = 0.0, Q = 0.0;
        for (int i = 0; i < 8; i++) { S += sh[i]; Q += qh[i]; }
        atomicAdd(&g_red[2], S); atomicAdd(&g_red[3], Q);
    }
}

__global__ void k_ln2(float* __restrict__ out, const float* __restrict__ w,
                      const float* __restrict__ b) {
    int i = blockIdx.x * blockDim.x + threadIdx.x;
    if (i < NN * C2) {
        double M = (double)NN * C2;
        double mean = g_red[2] / M;
        double var  = g_red[3] / M - mean * mean;
        float f = 1.f / ((float)sqrt(var > 0.0 ? var : 0.0) + 1e-5f);
        int c = i % C2;
        out[i] = (g_o2[i] - (float)mean) * f * w[c] + b[c];
    }
}

extern "C" void kernel_launch(void* const* d_in, const int* in_sizes, int n_in,
                              void* d_out, int out_size) {
    const int*   x    = (const int*)d_in[0];
    const int*   ei   = (const int*)d_in[1];
    const float* ea   = (const float*)d_in[2];
    const float* emb  = (const float*)d_in[3];
    const float* Wl1  = (const float*)d_in[4];
    const float* bl1  = (const float*)d_in[5];
    const float* Wr1  = (const float*)d_in[6];
    const float* br1  = (const float*)d_in[7];
    const float* We1  = (const float*)d_in[8];
    const float* att1 = (const float*)d_in[9];
    const float* bias1= (const float*)d_in[10];
    const float* ln1w = (const float*)d_in[11];
    const float* ln1b = (const float*)d_in[12];
    const float* Wl2  = (const float*)d_in[13];
    const float* bl2  = (const float*)d_in[14];
    const float* Wr2  = (const float*)d_in[15];
    const float* br2  = (const float*)d_in[16];
    const float* We2  = (const float*)d_in[17];
    const float* att2 = (const float*)d_in[18];
    const float* bias2= (const float*)d_in[19];
    const float* ln2w = (const float*)d_in[20];
    const float* ln2b = (const float*)d_in[21];
    float* out = (float*)d_out;

    const int node1_smem = (EMBP * C1 + 32 * EMBP * 2) * 4;     // ~66.6 KB
    const int edge1_smem = (10496 + 64 * 264) * 4;              // ~107.0 KB
    const int scan_smem  = NN * 4;                              // 200 KB
    cudaFuncSetAttribute(k_node1, cudaFuncAttributeMaxDynamicSharedMemorySize, node1_smem);
    cudaFuncSetAttribute(k_edge1, cudaFuncAttributeMaxDynamicSharedMemorySize, edge1_smem);
    cudaFuncSetAttribute(k_scan,  cudaFuncAttributeMaxDynamicSharedMemorySize, scan_smem);

    k_init<<<(5 * NN + 255) / 256, 256>>>();                               // 1
    k_deg<<<(EE + 255) / 256, 256>>>(ei);                                  // 2
    k_scan<<<1, 1024, scan_smem>>>();                                      // 3
    k_node1<<<(NN + 31) / 32, 256, node1_smem>>>(x, emb, Wl1, bl1, 0);     // 4 <- profiled
    k_node1<<<(NN + 31) / 32, 256, node1_smem>>>(x, emb, Wr1, br1, 1);     // 5
    k_fill<<<(EE + 255) / 256, 256>>>(ei);                                 // 6
    k_edge1<<<(EE + EB - 1) / EB, 128, edge1_smem>>>(ea, We1, att1);       // 7
    k_agg1<<<NN / 4, 256>>>(bias1);                                        // 8
    k_node2<<<NN / 16, 256>>>(Wl2, bl2, Wr2, br2, ln1w, ln1b);             // 9
    k_edge2<<<4096, 256>>>(ea, We2, att2);                                 // 10
    k_agg2<<<NN / 4, 256>>>(bias2);                                        // 11
    k_ln2<<<(NN * C2 + 255) / 256, 256>>>(out, ln2w, ln2b);                // 12
}

// round 13
// speedup vs baseline: 1.3433x; 1.3433x over previous
#include <cuda_runtime.h>

#define NN   50000
#define EE   500000
#define EMBD 50
#define EMBP 52
#define C1   256
#define C2   50
#define ED   28
#define TE   32

static __device__ float  g_xl[(size_t)NN * C1];
static __device__ float  g_xr[(size_t)NN * C1];
static __device__ float  g_h1[(size_t)NN * C1];
static __device__ float  g_logit[(size_t)EE * 4];
static __device__ int    g_off[NN + 1];
static __device__ int    g_cur[NN];
static __device__ int    g_eid[EE];
static __device__ int    g_esrc[EE];
static __device__ int    g_edst[EE];
static __device__ float  g_o2[(size_t)NN * C2];
static __device__ double g_red[4];

__device__ __forceinline__ float lrelu(float v) { return v > 0.f ? v : 0.2f * v; }

// ---- packed f32x2 helpers ----
__device__ __forceinline__ unsigned long long fma2(unsigned long long a,
                                                   unsigned long long b,
                                                   unsigned long long c) {
    unsigned long long d;
    asm("fma.rn.f32x2 %0, %1, %2, %3;" : "=l"(d) : "l"(a), "l"(b), "l"(c));
    return d;
}
__device__ __forceinline__ unsigned long long pack2(float x, float y) {
    unsigned long long d;
    asm("mov.b64 %0, {%1, %2};" : "=l"(d) : "r"(__float_as_int(x)), "r"(__float_as_int(y)));
    return d;
}
__device__ __forceinline__ float2 unpack2(unsigned long long v) {
    int lo, hi;
    asm("mov.b64 {%0, %1}, %2;" : "=r"(lo), "=r"(hi) : "l"(v));
    return make_float2(__int_as_float(lo), __int_as_float(hi));
}

__global__ void k_init() {
    int i = blockIdx.x * blockDim.x + threadIdx.x;
    if (i < NN) g_cur[i] = 0;
    if (i < 4)  g_red[i] = 0.0;
}

__global__ void k_deg(const int* __restrict__ ei) {
    int e = blockIdx.x * blockDim.x + threadIdx.x;
    if (e < EE) atomicAdd(&g_cur[ei[EE + e]], 1);
}

// coalesced single-block scan through 200KB smem
__global__ void k_scan() {
    extern __shared__ int si[];
    int t = threadIdx.x;
    for (int i = t; i < NN; i += 1024) si[i] = g_cur[i];
    __syncthreads();
    const int CH = (NN + 1023) / 1024;
    int lane = t & 31, w = t >> 5;
    int beg = t * CH;
    int end = beg + CH; if (end > NN) end = NN;
    int s = 0;
    for (int i = beg; i < end; i++) s += si[i];
    int incl = s;
#pragma unroll
    for (int off = 1; off < 32; off <<= 1) {
        int y = __shfl_up_sync(0xffffffffu, incl, off);
        if (lane >= off) incl += y;
    }
    __shared__ int ws[32];
    if (lane == 31) ws[w] = incl;
    __syncthreads();
    if (w == 0) {
        int v = ws[lane];
#pragma unroll
        for (int off = 1; off < 32; off <<= 1) {
            int y = __shfl_up_sync(0xffffffffu, v, off);
            if (lane >= off) v += y;
        }
        ws[lane] = v;
    }
    __syncthreads();
    int run = incl - s + (w > 0 ? ws[w - 1] : 0);
    for (int i = beg; i < end; i++) {
        int v = si[i];
        si[i] = run;
        run += v;
    }
    __syncthreads();
    for (int i = t; i < NN; i += 1024) {
        int v = si[i];
        g_off[i] = v;
        g_cur[i] = v;
    }
    if (t == 0) g_off[NN] = ws[31];
}

__global__ void k_fill(const int* __restrict__ ei) {
    int e = blockIdx.x * blockDim.x + threadIdx.x;
    if (e < EE) {
        int d = ei[EE + e];
        int pos = atomicAdd(&g_cur[d], 1);
        g_eid[pos]  = e;
        g_esrc[pos] = ei[e];
        g_edst[pos] = d;
    }
}

// node transform L1: gridDim.y=2 selects (Wl,bl)->xl vs (Wr,br)->xr
__global__ __launch_bounds__(256) void k_node1(const int* __restrict__ x,
                                               const float* __restrict__ emb,
                                               const float* __restrict__ Wl,
                                               const float* __restrict__ bl,
                                               const float* __restrict__ Wr,
                                               const float* __restrict__ br) {
    extern __shared__ float sm[];
    float* s_w  = sm;                       // EMBP*C1
    float* s_h2 = sm + EMBP * C1;           // 32*EMBP*2
    __shared__ int xs[32];
    int sel = blockIdx.y;
    const float* W    = sel ? Wr : Wl;
    const float* bvec = sel ? br : bl;
    int t = threadIdx.x;
    int nb = blockIdx.x * 32;
    if (t < 32) xs[t] = (nb + t < NN) ? x[nb + t] : 0;
    for (int i = t; i < EMBD * C1 / 4; i += 256)
        ((float4*)s_w)[i] = ((const float4*)W)[i];
    for (int i = t; i < (EMBP - EMBD) * C1 / 4; i += 256)
        ((float4*)s_w)[EMBD * C1 / 4 + i] = make_float4(0.f, 0.f, 0.f, 0.f);
    __syncthreads();
    for (int i = t; i < 32 * EMBP; i += 256) {
        int n = i / EMBP, k = i % EMBP;
        float v = (k < EMBD) ? emb[(size_t)xs[n] * EMBD + k] : 0.f;
        s_h2[i * 2] = v; s_h2[i * 2 + 1] = v;
    }
    __syncthreads();
    int cg = t & 63, g = t >> 6;
    int c0 = cg * 4;
    float4 bv = *(const float4*)&bvec[c0];
    ulonglong2 acc[8];
#pragma unroll
    for (int j = 0; j < 8; j++) {
        acc[j].x = pack2(bv.x, bv.y);
        acc[j].y = pack2(bv.z, bv.w);
    }
#pragma unroll 4
    for (int k = 0; k < EMBP; k++) {
        ulonglong2 w = *(const ulonglong2*)&s_w[k * C1 + c0];
#pragma unroll
        for (int j = 0; j < 8; j++) {
            unsigned long long h2 =
                *(const unsigned long long*)&s_h2[((g * 8 + j) * EMBP + k) * 2];
            acc[j].x = fma2(h2, w.x, acc[j].x);
            acc[j].y = fma2(h2, w.y, acc[j].y);
        }
    }
    float* dst = sel ? g_xr : g_xl;
#pragma unroll
    for (int j = 0; j < 8; j++) {
        int n = nb + g * 8 + j;
        if (n < NN) {
            float2 lo = unpack2(acc[j].x), hi = unpack2(acc[j].y);
            *(float4*)&dst[(size_t)n * C1 + c0] = make_float4(lo.x, lo.y, hi.x, hi.y);
        }
    }
}

// edge logits L1, CSR order: f32x2 with smem-duplicated ea splats (no max tracking)
__global__ __launch_bounds__(256) void k_edge1(const float* __restrict__ ea,
                                               const float* __restrict__ We,
                                               const float* __restrict__ att) {
    extern __shared__ float sm[];
    float* s_we  = sm;                      // 28*256 = 7168 floats
    float* s_ea2 = sm + 7168;               // 32*28*2 = 1792 floats
    __shared__ int s_src[TE], s_dst[TE], s_eid[TE];
    int t  = threadIdx.x;
    int eb = blockIdx.x * TE;
    if (t < TE) {
        s_src[t] = g_esrc[eb + t];
        s_dst[t] = g_edst[eb + t];
        s_eid[t] = g_eid[eb + t];
    }
    for (int i = t; i < ED * C1 / 4; i += 256)
        ((float4*)s_we)[i] = ((const float4*)We)[i];
    __syncthreads();
    for (int i = t; i < TE * ED; i += 256) {
        int e = i / ED, k = i - e * ED;
        float v = ea[(size_t)s_eid[e] * ED + k];
        s_ea2[i * 2] = v; s_ea2[i * 2 + 1] = v;
    }
    int cg = t & 63, eq = t >> 6;
    int c0 = cg * 4;
    ulonglong2 acc[8];
#pragma unroll
    for (int j = 0; j < 8; j++) {
        int e = eq * 8 + j;
        float4 a = *(const float4*)&g_xl[(size_t)s_src[e] * C1 + c0];
        float4 b = *(const float4*)&g_xr[(size_t)s_dst[e] * C1 + c0];
        acc[j].x = pack2(a.x + b.x, a.y + b.y);
        acc[j].y = pack2(a.z + b.z, a.w + b.w);
    }
    __syncthreads();
#pragma unroll 4
    for (int k = 0; k < ED; k++) {
        ulonglong2 w = *(const ulonglong2*)&s_we[k * C1 + c0];
#pragma unroll
        for (int j = 0; j < 8; j++) {
            unsigned long long e2 =
                *(const unsigned long long*)&s_ea2[((eq * 8 + j) * ED + k) * 2];
            acc[j].x = fma2(e2, w.x, acc[j].x);
            acc[j].y = fma2(e2, w.y, acc[j].y);
        }
    }
    float a0 = att[c0], a1 = att[c0 + 1], a2 = att[c0 + 2], a3 = att[c0 + 3];
    float part[8];
#pragma unroll
    for (int j = 0; j < 8; j++) {
        float2 lo = unpack2(acc[j].x), hi = unpack2(acc[j].y);
        part[j] = lrelu(lo.x) * a0 + lrelu(lo.y) * a1 +
                  lrelu(hi.x) * a2 + lrelu(hi.y) * a3;
    }
#pragma unroll
    for (int off = 8; off; off >>= 1) {
#pragma unroll
        for (int j = 0; j < 8; j++)
            part[j] += __shfl_down_sync(0xffffffffu, part[j], off);
    }
    int lane = t & 31;
    if ((lane & 15) == 0) {
        int h = cg >> 4;
#pragma unroll
        for (int j = 0; j < 8; j++) {
            int e = eq * 8 + j;
            g_logit[(size_t)(eb + e) * 4 + h] = part[j];   // CSR order
        }
    }
}

// aggregation L1 with fused softmax (no max shift) + fused LN stats
__global__ __launch_bounds__(256) void k_agg1(const float* __restrict__ bias) {
    int t = threadIdx.x;
    int n = blockIdx.x * 4 + (t >> 6);
    int t64 = t & 63;
    int lane = t & 31;
    int c0 = t64 * 4;
    int h  = t64 >> 4;
    int s = g_off[n], en = g_off[n + 1];
    float den = 0.f;
    float4 acc = make_float4(0.f, 0.f, 0.f, 0.f);
    for (int p = s; p < en; p++) {
        float ex = 0.f;
        if ((lane & 15) == 0) ex = expf(g_logit[(size_t)p * 4 + h]);
        ex = __shfl_sync(0xffffffffu, ex, lane & 16);
        den += ex;
        int src = g_esrc[p];
        float4 v = *(const float4*)&g_xl[(size_t)src * C1 + c0];
        acc.x += ex * v.x; acc.y += ex * v.y;
        acc.z += ex * v.z; acc.w += ex * v.w;
    }
    float inv = 1.f / (den + 1e-16f);
    float4 bv = *(const float4*)&bias[c0];
    float4 o;
    o.x = acc.x * inv + bv.x; o.y = acc.y * inv + bv.y;
    o.z = acc.z * inv + bv.z; o.w = acc.w * inv + bv.w;
    *(float4*)&g_h1[(size_t)n * C1 + c0] = o;
    float sv = o.x + o.y + o.z + o.w;
    float qv = o.x * o.x + o.y * o.y + o.z * o.z + o.w * o.w;
#pragma unroll
    for (int off = 16; off; off >>= 1) {
        sv += __shfl_down_sync(0xffffffffu, sv, off);
        qv += __shfl_down_sync(0xffffffffu, qv, off);
    }
    __shared__ double sh[8], qh[8];
    int w = t >> 5;
    if (lane == 0) { sh[w] = (double)sv; qh[w] = (double)qv; }
    __syncthreads();
    if (t == 0) {
        double S = 0.0, Q = 0.0;
        for (int i = 0; i < 8; i++) { S += sh[i]; Q += qh[i]; }
        atomicAdd(&g_red[0], S); atomicAdd(&g_red[1], Q);
    }
}

// node transform L2: fused LN1+ReLU, duplicated-h smem, f32x2
__global__ __launch_bounds__(256) void k_node2(const float* __restrict__ Wl,
                                               const float* __restrict__ bl,
                                               const float* __restrict__ Wr,
                                               const float* __restrict__ br,
                                               const float* __restrict__ lnw,
                                               const float* __restrict__ lnb) {
    __shared__ float hs2[16 * C1 * 2];
    __shared__ float s_lnw[C1], s_lnb[C1];
    __shared__ float s_mf[2];
    int t = threadIdx.x;
    int nb = blockIdx.x * 16;
    if (t < C1) { s_lnw[t] = lnw[t]; s_lnb[t] = lnb[t]; }
    if (t == 0) {
        double M = (double)NN * C1;
        double mean = g_red[0] / M;
        double var  = g_red[1] / M - mean * mean;
        s_mf[0] = (float)mean;
        s_mf[1] = 1.f / ((float)sqrt(var > 0.0 ? var : 0.0) + 1e-5f);
    }
    __syncthreads();
    float mean = s_mf[0], f = s_mf[1];
    for (int i = t; i < 16 * C1 / 4; i += 256) {
        float4 v = *(const float4*)&g_h1[(size_t)nb * C1 + (size_t)i * 4];
        int k = (i & 63) * 4;
        float4 w4 = *(const float4*)&s_lnw[k];
        float4 b4 = *(const float4*)&s_lnb[k];
        v.x = (v.x - mean) * f * w4.x + b4.x; v.x = v.x > 0.f ? v.x : 0.f;
        v.y = (v.y - mean) * f * w4.y + b4.y; v.y = v.y > 0.f ? v.y : 0.f;
        v.z = (v.z - mean) * f * w4.z + b4.z; v.z = v.z > 0.f ? v.z : 0.f;
        v.w = (v.w - mean) * f * w4.w + b4.w; v.w = v.w > 0.f ? v.w : 0.f;
        *(float4*)&hs2[i * 8]     = make_float4(v.x, v.x, v.y, v.y);
        *(float4*)&hs2[i * 8 + 4] = make_float4(v.z, v.z, v.w, v.w);
    }
    __syncthreads();
    int cp = t & 31;
    int c2 = cp * 2;
    int grp = t >> 5;
    int n0 = grp * 2, n1 = grp * 2 + 1;
    bool act = (c2 + 1) < C2;
    unsigned long long blv = 0, brv = 0;
    if (act) {
        blv = pack2(bl[c2], bl[c2 + 1]);
        brv = pack2(br[c2], br[c2 + 1]);
    }
    unsigned long long al0 = blv, al1 = blv, ar0 = brv, ar1 = brv;
#pragma unroll 4
    for (int k = 0; k < C1; k++) {
        unsigned long long wl = 0, wr = 0;
        if (act) {
            wl = *(const unsigned long long*)&Wl[k * C2 + c2];
            wr = *(const unsigned long long*)&Wr[k * C2 + c2];
        }
        unsigned long long h0 = *(const unsigned long long*)&hs2[(n0 * C1 + k) * 2];
        unsigned long long h1 = *(const unsigned long long*)&hs2[(n1 * C1 + k) * 2];
        al0 = fma2(h0, wl, al0);
        al1 = fma2(h1, wl, al1);
        ar0 = fma2(h0, wr, ar0);
        ar1 = fma2(h1, wr, ar1);
    }
    if (act) {
        float2 v;
        v = unpack2(al0); *(float2*)&g_xl[(size_t)(nb + n0) * C2 + c2] = v;
        v = unpack2(al1); *(float2*)&g_xl[(size_t)(nb + n1) * C2 + c2] = v;
        v = unpack2(ar0); *(float2*)&g_xr[(size_t)(nb + n0) * C2 + c2] = v;
        v = unpack2(ar1); *(float2*)&g_xr[(size_t)(nb + n1) * C2 + c2] = v;
    }
}

// edge logits L2 in CSR order, warp per edge (no max tracking)
__global__ __launch_bounds__(256) void k_edge2(const float* __restrict__ ea,
                                               const float* __restrict__ We,
                                               const float* __restrict__ att) {
    int lane = threadIdx.x & 31;
    int gw = (blockIdx.x * blockDim.x + threadIdx.x) >> 5;
    int nw = (gridDim.x * blockDim.x) >> 5;
    int c0 = lane * 2;
    bool act = c0 < C2;
    float2 w[ED];
#pragma unroll
    for (int k = 0; k < ED; k++)
        w[k] = act ? *(const float2*)&We[k * C2 + c0] : make_float2(0.f, 0.f);
    float2 a2 = act ? *(const float2*)&att[c0] : make_float2(0.f, 0.f);
    for (int p = gw; p < EE; p += nw) {
        int src = g_esrc[p], dst = g_edst[p], e = g_eid[p];
        float eav = (lane < ED) ? ea[(size_t)e * ED + lane] : 0.f;
        float mx = 0.f, my = 0.f;
        if (act) {
            float2 u = *(const float2*)&g_xl[(size_t)src * C2 + c0];
            float2 v = *(const float2*)&g_xr[(size_t)dst * C2 + c0];
            mx = u.x + v.x; my = u.y + v.y;
        }
#pragma unroll
        for (int k = 0; k < ED; k++) {
            float a = __shfl_sync(0xffffffffu, eav, k);
            mx += a * w[k].x; my += a * w[k].y;
        }
        float pt = lrelu(mx) * a2.x + lrelu(my) * a2.y;
#pragma unroll
        for (int off = 16; off; off >>= 1) pt += __shfl_down_sync(0xffffffffu, pt, off);
        if (lane == 0) g_logit[p] = pt;                 // CSR order
    }
}

// aggregation L2 with fused softmax (no max shift) + fused LN stats
__global__ __launch_bounds__(256) void k_agg2(const float* __restrict__ bias) {
    int t = threadIdx.x;
    int n = blockIdx.x * 4 + (t >> 6);
    int t64 = t & 63;
    int lane = t & 31;
    int s = g_off[n], en = g_off[n + 1];
    bool act = t64 < C2;
    float den = 0.f, acc = 0.f;
    for (int p = s; p < en; p++) {
        float ex = 0.f;
        if (lane == 0) ex = expf(g_logit[p]);
        ex = __shfl_sync(0xffffffffu, ex, 0);
        den += ex;
        int src = g_esrc[p];
        if (act) acc += ex * g_xl[(size_t)src * C2 + t64];
    }
    float o = 0.f;
    if (act) {
        o = acc / (den + 1e-16f) + bias[t64];
        g_o2[(size_t)n * C2 + t64] = o;
    }
    float sv = o, qv = o * o;
#pragma unroll
    for (int off = 16; off; off >>= 1) {
        sv += __shfl_down_sync(0xffffffffu, sv, off);
        qv += __shfl_down_sync(0xffffffffu, qv, off);
    }
    __shared__ double sh[8], qh[8];
    int w = t >> 5;
    if (lane == 0) { sh[w] = (double)sv; qh[w] = (double)qv; }
    __syncthreads();
    if (t == 0) {
        double S = 0.0, Q = 0.0;
        for (int i = 0; i < 8; i++) { S += sh[i]; Q += qh[i]; }
        atomicAdd(&g_red[2], S); atomicAdd(&g_red[3], Q);
    }
}

__global__ void k_ln2(float* __restrict__ out, const float* __restrict__ w,
                      const float* __restrict__ b) {
    int i = blockIdx.x * blockDim.x + threadIdx.x;
    if (i < NN * C2) {
        double M = (double)NN * C2;
        double mean = g_red[2] / M;
        double var  = g_red[3] / M - mean * mean;
        float f = 1.f / ((float)sqrt(var > 0.0 ? var : 0.0) + 1e-5f);
        int c = i % C2;
        out[i] = (g_o2[i] - (float)mean) * f * w[c] + b[c];
    }
}

extern "C" void kernel_launch(void* const* d_in, const int* in_sizes, int n_in,
                              void* d_out, int out_size) {
    const int*   x    = (const int*)d_in[0];
    const int*   ei   = (const int*)d_in[1];
    const float* ea   = (const float*)d_in[2];
    const float* emb  = (const float*)d_in[3];
    const float* Wl1  = (const float*)d_in[4];
    const float* bl1  = (const float*)d_in[5];
    const float* Wr1  = (const float*)d_in[6];
    const float* br1  = (const float*)d_in[7];
    const float* We1  = (const float*)d_in[8];
    const float* att1 = (const float*)d_in[9];
    const float* bias1= (const float*)d_in[10];
    const float* ln1w = (const float*)d_in[11];
    const float* ln1b = (const float*)d_in[12];
    const float* Wl2  = (const float*)d_in[13];
    const float* bl2  = (const float*)d_in[14];
    const float* Wr2  = (const float*)d_in[15];
    const float* br2  = (const float*)d_in[16];
    const float* We2  = (const float*)d_in[17];
    const float* att2 = (const float*)d_in[18];
    const float* bias2= (const float*)d_in[19];
    const float* ln2w = (const float*)d_in[20];
    const float* ln2b = (const float*)d_in[21];
    float* out = (float*)d_out;

    const int node1_smem = (EMBP * C1 + 32 * EMBP * 2) * 4;   // ~66.6 KB
    const int edge1_smem = (7168 + TE * ED * 2) * 4;          // ~35.8 KB
    const int scan_smem  = NN * 4;                            // 200 KB
    cudaFuncSetAttribute(k_node1, cudaFuncAttributeMaxDynamicSharedMemorySize, node1_smem);
    cudaFuncSetAttribute(k_edge1, cudaFuncAttributeMaxDynamicSharedMemorySize, edge1_smem);
    cudaFuncSetAttribute(k_scan,  cudaFuncAttributeMaxDynamicSharedMemorySize, scan_smem);

    dim3 n1grid((NN + 31) / 32, 2);

    k_init<<<(NN + 255) / 256, 256>>>();                                   // 1
    k_deg<<<(EE + 255) / 256, 256>>>(ei);                                  // 2
    k_scan<<<1, 1024, scan_smem>>>();                                      // 3
    k_node1<<<n1grid, 256, node1_smem>>>(x, emb, Wl1, bl1, Wr1, br1);      // 4 <- profiled
    k_fill<<<(EE + 255) / 256, 256>>>(ei);                                 // 5
    k_edge1<<<EE / TE, 256, edge1_smem>>>(ea, We1, att1);                  // 6
    k_agg1<<<NN / 4, 256>>>(bias1);                                        // 7
    k_node2<<<NN / 16, 256>>>(Wl2, bl2, Wr2, br2, ln1w, ln1b);             // 8
    k_edge2<<<4096, 256>>>(ea, We2, att2);                                 // 9
    k_agg2<<<NN / 4, 256>>>(bias2);                                        // 10
    k_ln2<<<(NN * C2 + 255) / 256, 256>>>(out, ln2w, ln2b);                // 11
}

// round 14
// speedup vs baseline: 1.4190x; 1.0564x over previous
#include <cuda_runtime.h>

#define NN   50000
#define EE   500000
#define EMBD 50
#define EMBP 52
#define C1   256
#define C2   50
#define ED   28
#define TE   32

static __device__ float  g_xl[(size_t)NN * C1];
static __device__ float  g_xr[(size_t)NN * C1];
static __device__ float  g_h1[(size_t)NN * C1];
static __device__ float  g_logit[(size_t)EE * 4];
static __device__ float  g_den[(size_t)5 * NN];
static __device__ int    g_off[NN + 1];
static __device__ int    g_cur[NN];
static __device__ int    g_eid[EE];
static __device__ int    g_esrc[EE];
static __device__ int    g_edst[EE];
static __device__ float  g_o2[(size_t)NN * C2];
static __device__ double g_red[4];

__device__ __forceinline__ float lrelu(float v) { return v > 0.f ? v : 0.2f * v; }

// ---- packed f32x2 helpers ----
__device__ __forceinline__ unsigned long long fma2(unsigned long long a,
                                                   unsigned long long b,
                                                   unsigned long long c) {
    unsigned long long d;
    asm("fma.rn.f32x2 %0, %1, %2, %3;" : "=l"(d) : "l"(a), "l"(b), "l"(c));
    return d;
}
__device__ __forceinline__ unsigned long long pack2(float x, float y) {
    unsigned long long d;
    asm("mov.b64 %0, {%1, %2};" : "=l"(d) : "r"(__float_as_int(x)), "r"(__float_as_int(y)));
    return d;
}
__device__ __forceinline__ float2 unpack2(unsigned long long v) {
    int lo, hi;
    asm("mov.b64 {%0, %1}, %2;" : "=r"(lo), "=r"(hi) : "l"(v));
    return make_float2(__int_as_float(lo), __int_as_float(hi));
}

__global__ void k_init() {
    int i = blockIdx.x * blockDim.x + threadIdx.x;
    if (i < 5 * NN) g_den[i] = 0.f;
    if (i < NN) g_cur[i] = 0;
    if (i < 4)  g_red[i] = 0.0;
}

__global__ void k_deg(const int* __restrict__ ei) {
    int e = blockIdx.x * blockDim.x + threadIdx.x;
    if (e < EE) atomicAdd(&g_cur[ei[EE + e]], 1);
}

// coalesced single-block scan through 200KB smem
__global__ void k_scan() {
    extern __shared__ int si[];
    int t = threadIdx.x;
    for (int i = t; i < NN; i += 1024) si[i] = g_cur[i];
    __syncthreads();
    const int CH = (NN + 1023) / 1024;
    int lane = t & 31, w = t >> 5;
    int beg = t * CH;
    int end = beg + CH; if (end > NN) end = NN;
    int s = 0;
    for (int i = beg; i < end; i++) s += si[i];
    int incl = s;
#pragma unroll
    for (int off = 1; off < 32; off <<= 1) {
        int y = __shfl_up_sync(0xffffffffu, incl, off);
        if (lane >= off) incl += y;
    }
    __shared__ int ws[32];
    if (lane == 31) ws[w] = incl;
    __syncthreads();
    if (w == 0) {
        int v = ws[lane];
#pragma unroll
        for (int off = 1; off < 32; off <<= 1) {
            int y = __shfl_up_sync(0xffffffffu, v, off);
            if (lane >= off) v += y;
        }
        ws[lane] = v;
    }
    __syncthreads();
    int run = incl - s + (w > 0 ? ws[w - 1] : 0);
    for (int i = beg; i < end; i++) {
        int v = si[i];
        si[i] = run;
        run += v;
    }
    __syncthreads();
    for (int i = t; i < NN; i += 1024) {
        int v = si[i];
        g_off[i] = v;
        g_cur[i] = v;
    }
    if (t == 0) g_off[NN] = ws[31];
}

__global__ void k_fill(const int* __restrict__ ei) {
    int e = blockIdx.x * blockDim.x + threadIdx.x;
    if (e < EE) {
        int d = ei[EE + e];
        int pos = atomicAdd(&g_cur[d], 1);
        g_eid[pos]  = e;
        g_esrc[pos] = ei[e];
        g_edst[pos] = d;
    }
}

// node transform L1: gridDim.y=2 selects (Wl,bl)->xl vs (Wr,br)->xr
__global__ __launch_bounds__(256) void k_node1(const int* __restrict__ x,
                                               const float* __restrict__ emb,
                                               const float* __restrict__ Wl,
                                               const float* __restrict__ bl,
                                               const float* __restrict__ Wr,
                                               const float* __restrict__ br) {
    extern __shared__ float sm[];
    float* s_w  = sm;
    float* s_h2 = sm + EMBP * C1;
    __shared__ int xs[32];
    int sel = blockIdx.y;
    const float* W    = sel ? Wr : Wl;
    const float* bvec = sel ? br : bl;
    int t = threadIdx.x;
    int nb = blockIdx.x * 32;
    if (t < 32) xs[t] = (nb + t < NN) ? x[nb + t] : 0;
    for (int i = t; i < EMBD * C1 / 4; i += 256)
        ((float4*)s_w)[i] = ((const float4*)W)[i];
    for (int i = t; i < (EMBP - EMBD) * C1 / 4; i += 256)
        ((float4*)s_w)[EMBD * C1 / 4 + i] = make_float4(0.f, 0.f, 0.f, 0.f);
    __syncthreads();
    for (int i = t; i < 32 * EMBP; i += 256) {
        int n = i / EMBP, k = i % EMBP;
        float v = (k < EMBD) ? emb[(size_t)xs[n] * EMBD + k] : 0.f;
        s_h2[i * 2] = v; s_h2[i * 2 + 1] = v;
    }
    __syncthreads();
    int cg = t & 63, g = t >> 6;
    int c0 = cg * 4;
    float4 bv = *(const float4*)&bvec[c0];
    ulonglong2 acc[8];
#pragma unroll
    for (int j = 0; j < 8; j++) {
        acc[j].x = pack2(bv.x, bv.y);
        acc[j].y = pack2(bv.z, bv.w);
    }
#pragma unroll 4
    for (int k = 0; k < EMBP; k++) {
        ulonglong2 w = *(const ulonglong2*)&s_w[k * C1 + c0];
#pragma unroll
        for (int j = 0; j < 8; j++) {
            unsigned long long h2 =
                *(const unsigned long long*)&s_h2[((g * 8 + j) * EMBP + k) * 2];
            acc[j].x = fma2(h2, w.x, acc[j].x);
            acc[j].y = fma2(h2, w.y, acc[j].y);
        }
    }
    float* dst = sel ? g_xr : g_xl;
#pragma unroll
    for (int j = 0; j < 8; j++) {
        int n = nb + g * 8 + j;
        if (n < NN) {
            float2 lo = unpack2(acc[j].x), hi = unpack2(acc[j].y);
            *(float4*)&dst[(size_t)n * C1 + c0] = make_float4(lo.x, lo.y, hi.x, hi.y);
        }
    }
}

// edge logits L1, CSR order: writes exp(logit) and accumulates denominator
__global__ __launch_bounds__(256, 4) void k_edge1(const float* __restrict__ ea,
                                                  const float* __restrict__ We,
                                                  const float* __restrict__ att) {
    extern __shared__ float sm[];
    float* s_we  = sm;                      // 28*256 = 7168 floats
    float* s_ea2 = sm + 7168;               // 32*28*2 = 1792 floats
    __shared__ int s_src[TE], s_dst[TE], s_eid[TE];
    int t  = threadIdx.x;
    int eb = blockIdx.x * TE;
    if (t < TE) {
        s_src[t] = g_esrc[eb + t];
        s_dst[t] = g_edst[eb + t];
        s_eid[t] = g_eid[eb + t];
    }
    for (int i = t; i < ED * C1 / 4; i += 256)
        ((float4*)s_we)[i] = ((const float4*)We)[i];
    __syncthreads();
    for (int i = t; i < TE * ED; i += 256) {
        int e = i / ED, k = i - e * ED;
        float v = ea[(size_t)s_eid[e] * ED + k];
        s_ea2[i * 2] = v; s_ea2[i * 2 + 1] = v;
    }
    int cg = t & 63, eq = t >> 6;
    int c0 = cg * 4;
    ulonglong2 acc[8];
#pragma unroll
    for (int j = 0; j < 8; j++) {
        int e = eq * 8 + j;
        float4 a = *(const float4*)&g_xl[(size_t)s_src[e] * C1 + c0];
        float4 b = *(const float4*)&g_xr[(size_t)s_dst[e] * C1 + c0];
        acc[j].x = pack2(a.x + b.x, a.y + b.y);
        acc[j].y = pack2(a.z + b.z, a.w + b.w);
    }
    __syncthreads();
#pragma unroll 4
    for (int k = 0; k < ED; k++) {
        ulonglong2 w = *(const ulonglong2*)&s_we[k * C1 + c0];
#pragma unroll
        for (int j = 0; j < 8; j++) {
            unsigned long long e2 =
                *(const unsigned long long*)&s_ea2[((eq * 8 + j) * ED + k) * 2];
            acc[j].x = fma2(e2, w.x, acc[j].x);
            acc[j].y = fma2(e2, w.y, acc[j].y);
        }
    }
    float a0 = att[c0], a1 = att[c0 + 1], a2 = att[c0 + 2], a3 = att[c0 + 3];
    float part[8];
#pragma unroll
    for (int j = 0; j < 8; j++) {
        float2 lo = unpack2(acc[j].x), hi = unpack2(acc[j].y);
        part[j] = lrelu(lo.x) * a0 + lrelu(lo.y) * a1 +
                  lrelu(hi.x) * a2 + lrelu(hi.y) * a3;
    }
#pragma unroll
    for (int off = 8; off; off >>= 1) {
#pragma unroll
        for (int j = 0; j < 8; j++)
            part[j] += __shfl_down_sync(0xffffffffu, part[j], off);
    }
    int lane = t & 31;
    if ((lane & 15) == 0) {
        int h = cg >> 4;
#pragma unroll
        for (int j = 0; j < 8; j++) {
            int e = eq * 8 + j;
            float ex = expf(part[j]);
            g_logit[(size_t)(eb + e) * 4 + h] = ex;     // alpha numerator, CSR order
            atomicAdd(&g_den[s_dst[e] * 4 + h], ex);
        }
    }
}

// aggregation L1: pure weighted gather (alpha precomputed) + fused LN stats
__global__ __launch_bounds__(256) void k_agg1(const float* __restrict__ bias) {
    int t = threadIdx.x;
    int n = blockIdx.x * 4 + (t >> 6);
    int t64 = t & 63;
    int lane = t & 31;
    int c0 = t64 * 4;
    int h  = t64 >> 4;
    int s = g_off[n], en = g_off[n + 1];
    float4 acc = make_float4(0.f, 0.f, 0.f, 0.f);
    for (int p = s; p < en; p++) {
        float ex = g_logit[(size_t)p * 4 + h];          // broadcast within 16-group
        int src = g_esrc[p];
        float4 v = *(const float4*)&g_xl[(size_t)src * C1 + c0];
        acc.x += ex * v.x; acc.y += ex * v.y;
        acc.z += ex * v.z; acc.w += ex * v.w;
    }
    float inv = 1.f / (g_den[n * 4 + h] + 1e-16f);
    float4 bv = *(const float4*)&bias[c0];
    float4 o;
    o.x = acc.x * inv + bv.x; o.y = acc.y * inv + bv.y;
    o.z = acc.z * inv + bv.z; o.w = acc.w * inv + bv.w;
    *(float4*)&g_h1[(size_t)n * C1 + c0] = o;
    float sv = o.x + o.y + o.z + o.w;
    float qv = o.x * o.x + o.y * o.y + o.z * o.z + o.w * o.w;
#pragma unroll
    for (int off = 16; off; off >>= 1) {
        sv += __shfl_down_sync(0xffffffffu, sv, off);
        qv += __shfl_down_sync(0xffffffffu, qv, off);
    }
    __shared__ double sh[8], qh[8];
    int w = t >> 5;
    if (lane == 0) { sh[w] = (double)sv; qh[w] = (double)qv; }
    __syncthreads();
    if (t == 0) {
        double S = 0.0, Q = 0.0;
        for (int i = 0; i < 8; i++) { S += sh[i]; Q += qh[i]; }
        atomicAdd(&g_red[0], S); atomicAdd(&g_red[1], Q);
    }
}

// node transform L2: fused LN1+ReLU, duplicated-h smem, f32x2
__global__ __launch_bounds__(256) void k_node2(const float* __restrict__ Wl,
                                               const float* __restrict__ bl,
                                               const float* __restrict__ Wr,
                                               const float* __restrict__ br,
                                               const float* __restrict__ lnw,
                                               const float* __restrict__ lnb) {
    __shared__ float hs2[16 * C1 * 2];
    __shared__ float s_lnw[C1], s_lnb[C1];
    __shared__ float s_mf[2];
    int t = threadIdx.x;
    int nb = blockIdx.x * 16;
    if (t < C1) { s_lnw[t] = lnw[t]; s_lnb[t] = lnb[t]; }
    if (t == 0) {
        double M = (double)NN * C1;
        double mean = g_red[0] / M;
        double var  = g_red[1] / M - mean * mean;
        s_mf[0] = (float)mean;
        s_mf[1] = 1.f / ((float)sqrt(var > 0.0 ? var : 0.0) + 1e-5f);
    }
    __syncthreads();
    float mean = s_mf[0], f = s_mf[1];
    for (int i = t; i < 16 * C1 / 4; i += 256) {
        float4 v = *(const float4*)&g_h1[(size_t)nb * C1 + (size_t)i * 4];
        int k = (i & 63) * 4;
        float4 w4 = *(const float4*)&s_lnw[k];
        float4 b4 = *(const float4*)&s_lnb[k];
        v.x = (v.x - mean) * f * w4.x + b4.x; v.x = v.x > 0.f ? v.x : 0.f;
        v.y = (v.y - mean) * f * w4.y + b4.y; v.y = v.y > 0.f ? v.y : 0.f;
        v.z = (v.z - mean) * f * w4.z + b4.z; v.z = v.z > 0.f ? v.z : 0.f;
        v.w = (v.w - mean) * f * w4.w + b4.w; v.w = v.w > 0.f ? v.w : 0.f;
        *(float4*)&hs2[i * 8]     = make_float4(v.x, v.x, v.y, v.y);
        *(float4*)&hs2[i * 8 + 4] = make_float4(v.z, v.z, v.w, v.w);
    }
    __syncthreads();
    int cp = t & 31;
    int c2 = cp * 2;
    int grp = t >> 5;
    int n0 = grp * 2, n1 = grp * 2 + 1;
    bool act = (c2 + 1) < C2;
    unsigned long long blv = 0, brv = 0;
    if (act) {
        blv = pack2(bl[c2], bl[c2 + 1]);
        brv = pack2(br[c2], br[c2 + 1]);
    }
    unsigned long long al0 = blv, al1 = blv, ar0 = brv, ar1 = brv;
#pragma unroll 4
    for (int k = 0; k < C1; k++) {
        unsigned long long wl = 0, wr = 0;
        if (act) {
            wl = *(const unsigned long long*)&Wl[k * C2 + c2];
            wr = *(const unsigned long long*)&Wr[k * C2 + c2];
        }
        unsigned long long h0 = *(const unsigned long long*)&hs2[(n0 * C1 + k) * 2];
        unsigned long long h1 = *(const unsigned long long*)&hs2[(n1 * C1 + k) * 2];
        al0 = fma2(h0, wl, al0);
        al1 = fma2(h1, wl, al1);
        ar0 = fma2(h0, wr, ar0);
        ar1 = fma2(h1, wr, ar1);
    }
    if (act) {
        float2 v;
        v = unpack2(al0); *(float2*)&g_xl[(size_t)(nb + n0) * C2 + c2] = v;
        v = unpack2(al1); *(float2*)&g_xl[(size_t)(nb + n1) * C2 + c2] = v;
        v = unpack2(ar0); *(float2*)&g_xr[(size_t)(nb + n0) * C2 + c2] = v;
        v = unpack2(ar1); *(float2*)&g_xr[(size_t)(nb + n1) * C2 + c2] = v;
    }
}

// edge logits L2, CSR order: writes exp(logit), accumulates denominator
__global__ __launch_bounds__(256) void k_edge2(const float* __restrict__ ea,
                                               const float* __restrict__ We,
                                               const float* __restrict__ att) {
    int lane = threadIdx.x & 31;
    int gw = (blockIdx.x * blockDim.x + threadIdx.x) >> 5;
    int nw = (gridDim.x * blockDim.x) >> 5;
    int c0 = lane * 2;
    bool act = c0 < C2;
    float2 w[ED];
#pragma unroll
    for (int k = 0; k < ED; k++)
        w[k] = act ? *(const float2*)&We[k * C2 + c0] : make_float2(0.f, 0.f);
    float2 a2 = act ? *(const float2*)&att[c0] : make_float2(0.f, 0.f);
    for (int p = gw; p < EE; p += nw) {
        int src = g_esrc[p], dst = g_edst[p], e = g_eid[p];
        float eav = (lane < ED) ? ea[(size_t)e * ED + lane] : 0.f;
        float mx = 0.f, my = 0.f;
        if (act) {
            float2 u = *(const float2*)&g_xl[(size_t)src * C2 + c0];
            float2 v = *(const float2*)&g_xr[(size_t)dst * C2 + c0];
            mx = u.x + v.x; my = u.y + v.y;
        }
#pragma unroll
        for (int k = 0; k < ED; k++) {
            float a = __shfl_sync(0xffffffffu, eav, k);
            mx += a * w[k].x; my += a * w[k].y;
        }
        float pt = lrelu(mx) * a2.x + lrelu(my) * a2.y;
#pragma unroll
        for (int off = 16; off; off >>= 1) pt += __shfl_down_sync(0xffffffffu, pt, off);
        if (lane == 0) {
            float ex = expf(pt);
            g_logit[p] = ex;                 // alpha numerator, CSR order
            atomicAdd(&g_den[4 * NN + dst], ex);
        }
    }
}

// aggregation L2: pure weighted gather + fused LN stats
__global__ __launch_bounds__(256) void k_agg2(const float* __restrict__ bias) {
    int t = threadIdx.x;
    int n = blockIdx.x * 4 + (t >> 6);
    int t64 = t & 63;
    int lane = t & 31;
    int s = g_off[n], en = g_off[n + 1];
    bool act = t64 < C2;
    float acc = 0.f;
    for (int p = s; p < en; p++) {
        float ex = g_logit[p];               // broadcast
        int src = g_esrc[p];
        if (act) acc += ex * g_xl[(size_t)src * C2 + t64];
    }
    float o = 0.f;
    if (act) {
        o = acc / (g_den[4 * NN + n] + 1e-16f) + bias[t64];
        g_o2[(size_t)n * C2 + t64] = o;
    }
    float sv = o, qv = o * o;
#pragma unroll
    for (int off = 16; off; off >>= 1) {
        sv += __shfl_down_sync(0xffffffffu, sv, off);
        qv += __shfl_down_sync(0xffffffffu, qv, off);
    }
    __shared__ double sh[8], qh[8];
    int w = t >> 5;
    if (lane == 0) { sh[w] = (double)sv; qh[w] = (double)qv; }
    __syncthreads();
    if (t == 0) {
        double S = 0.0, Q = 0.0;
        for (int i = 0; i < 8; i++) { S += sh[i]; Q += qh[i]; }
        atomicAdd(&g_red[2], S); atomicAdd(&g_red[3], Q);
    }
}

__global__ void k_ln2(float* __restrict__ out, const float* __restrict__ w,
                      const float* __restrict__ b) {
    int i = blockIdx.x * blockDim.x + threadIdx.x;
    if (i < NN * C2) {
        double M = (double)NN * C2;
        double mean = g_red[2] / M;
        double var  = g_red[3] / M - mean * mean;
        float f = 1.f / ((float)sqrt(var > 0.0 ? var : 0.0) + 1e-5f);
        int c = i % C2;
        out[i] = (g_o2[i] - (float)mean) * f * w[c] + b[c];
    }
}

extern "C" void kernel_launch(void* const* d_in, const int* in_sizes, int n_in,
                              void* d_out, int out_size) {
    const int*   x    = (const int*)d_in[0];
    const int*   ei   = (const int*)d_in[1];
    const float* ea   = (const float*)d_in[2];
    const float* emb  = (const float*)d_in[3];
    const float* Wl1  = (const float*)d_in[4];
    const float* bl1  = (const float*)d_in[5];
    const float* Wr1  = (const float*)d_in[6];
    const float* br1  = (const float*)d_in[7];
    const float* We1  = (const float*)d_in[8];
    const float* att1 = (const float*)d_in[9];
    const float* bias1= (const float*)d_in[10];
    const float* ln1w = (const float*)d_in[11];
    const float* ln1b = (const float*)d_in[12];
    const float* Wl2  = (const float*)d_in[13];
    const float* bl2  = (const float*)d_in[14];
    const float* Wr2  = (const float*)d_in[15];
    const float* br2  = (const float*)d_in[16];
    const float* We2  = (const float*)d_in[17];
    const float* att2 = (const float*)d_in[18];
    const float* bias2= (const float*)d_in[19];
    const float* ln2w = (const float*)d_in[20];
    const float* ln2b = (const float*)d_in[21];
    float* out = (float*)d_out;

    const int node1_smem = (EMBP * C1 + 32 * EMBP * 2) * 4;   // ~66.6 KB
    const int edge1_smem = (7168 + TE * ED * 2) * 4;          // ~35.8 KB
    const int scan_smem  = NN * 4;                            // 200 KB
    cudaFuncSetAttribute(k_node1, cudaFuncAttributeMaxDynamicSharedMemorySize, node1_smem);
    cudaFuncSetAttribute(k_edge1, cudaFuncAttributeMaxDynamicSharedMemorySize, edge1_smem);
    cudaFuncSetAttribute(k_scan,  cudaFuncAttributeMaxDynamicSharedMemorySize, scan_smem);

    dim3 n1grid((NN + 31) / 32, 2);

    k_init<<<(5 * NN + 255) / 256, 256>>>();                               // 1
    k_deg<<<(EE + 255) / 256, 256>>>(ei);                                  // 2
    k_scan<<<1, 1024, scan_smem>>>();                                      // 3
    k_node1<<<n1grid, 256, node1_smem>>>(x, emb, Wl1, bl1, Wr1, br1);      // 4
    k_fill<<<(EE + 255) / 256, 256>>>(ei);                                 // 5
    k_edge1<<<EE / TE, 256, edge1_smem>>>(ea, We1, att1);                  // 6
    k_agg1<<<NN / 4, 256>>>(bias1);                                        // 7
    k_node2<<<NN / 16, 256>>>(Wl2, bl2, Wr2, br2, ln1w, ln1b);             // 8
    k_edge2<<<4096, 256>>>(ea, We2, att2);                                 // 9
    k_agg2<<<NN / 4, 256>>>(bias2);                                        // 10
    k_ln2<<<(NN * C2 + 255) / 256, 256>>>(out, ln2w, ln2b);                // 11
}

// round 15
// speedup vs baseline: 1.4713x; 1.0369x over previous
#include <cuda_runtime.h>

#define NN   50000
#define EE   500000
#define EMBD 50
#define EMBP 52
#define C1   256
#define C2   50
#define ED   28
#define TE   32
#define TE2  32

static __device__ float  g_xl[(size_t)NN * C1];
static __device__ float  g_xr[(size_t)NN * C1];
static __device__ float  g_h1[(size_t)NN * C1];
static __device__ float  g_logit[(size_t)EE * 4];
static __device__ float  g_den[(size_t)5 * NN];
static __device__ int    g_off[NN + 1];
static __device__ int    g_cur[NN];
static __device__ int    g_eid[EE];
static __device__ int    g_esrc[EE];
static __device__ int    g_edst[EE];
static __device__ float  g_o2[(size_t)NN * C2];
static __device__ double g_red[4];

__device__ __forceinline__ float lrelu(float v) { return v > 0.f ? v : 0.2f * v; }

// ---- packed f32x2 helpers ----
__device__ __forceinline__ unsigned long long fma2(unsigned long long a,
                                                   unsigned long long b,
                                                   unsigned long long c) {
    unsigned long long d;
    asm("fma.rn.f32x2 %0, %1, %2, %3;" : "=l"(d) : "l"(a), "l"(b), "l"(c));
    return d;
}
__device__ __forceinline__ unsigned long long pack2(float x, float y) {
    unsigned long long d;
    asm("mov.b64 %0, {%1, %2};" : "=l"(d) : "r"(__float_as_int(x)), "r"(__float_as_int(y)));
    return d;
}
__device__ __forceinline__ float2 unpack2(unsigned long long v) {
    int lo, hi;
    asm("mov.b64 {%0, %1}, %2;" : "=r"(lo), "=r"(hi) : "l"(v));
    return make_float2(__int_as_float(lo), __int_as_float(hi));
}

__global__ void k_init() {
    int i = blockIdx.x * blockDim.x + threadIdx.x;
    if (i < 5 * NN) g_den[i] = 0.f;
    if (i < NN) g_cur[i] = 0;
    if (i < 4)  g_red[i] = 0.0;
}

__global__ void k_deg(const int* __restrict__ ei) {
    int e = blockIdx.x * blockDim.x + threadIdx.x;
    if (e < EE) atomicAdd(&g_cur[ei[EE + e]], 1);
}

// coalesced single-block scan through 200KB smem
__global__ void k_scan() {
    extern __shared__ int si[];
    int t = threadIdx.x;
    for (int i = t; i < NN; i += 1024) si[i] = g_cur[i];
    __syncthreads();
    const int CH = (NN + 1023) / 1024;
    int lane = t & 31, w = t >> 5;
    int beg = t * CH;
    int end = beg + CH; if (end > NN) end = NN;
    int s = 0;
    for (int i = beg; i < end; i++) s += si[i];
    int incl = s;
#pragma unroll
    for (int off = 1; off < 32; off <<= 1) {
        int y = __shfl_up_sync(0xffffffffu, incl, off);
        if (lane >= off) incl += y;
    }
    __shared__ int ws[32];
    if (lane == 31) ws[w] = incl;
    __syncthreads();
    if (w == 0) {
        int v = ws[lane];
#pragma unroll
        for (int off = 1; off < 32; off <<= 1) {
            int y = __shfl_up_sync(0xffffffffu, v, off);
            if (lane >= off) v += y;
        }
        ws[lane] = v;
    }
    __syncthreads();
    int run = incl - s + (w > 0 ? ws[w - 1] : 0);
    for (int i = beg; i < end; i++) {
        int v = si[i];
        si[i] = run;
        run += v;
    }
    __syncthreads();
    for (int i = t; i < NN; i += 1024) {
        int v = si[i];
        g_off[i] = v;
        g_cur[i] = v;
    }
    if (t == 0) g_off[NN] = ws[31];
}

__global__ void k_fill(const int* __restrict__ ei) {
    int e = blockIdx.x * blockDim.x + threadIdx.x;
    if (e < EE) {
        int d = ei[EE + e];
        int pos = atomicAdd(&g_cur[d], 1);
        g_eid[pos]  = e;
        g_esrc[pos] = ei[e];
        g_edst[pos] = d;
    }
}

// node transform L1: gridDim.y=2 selects (Wl,bl)->xl vs (Wr,br)->xr
__global__ __launch_bounds__(256) void k_node1(const int* __restrict__ x,
                                               const float* __restrict__ emb,
                                               const float* __restrict__ Wl,
                                               const float* __restrict__ bl,
                                               const float* __restrict__ Wr,
                                               const float* __restrict__ br) {
    extern __shared__ float sm[];
    float* s_w  = sm;
    float* s_h2 = sm + EMBP * C1;
    __shared__ int xs[32];
    int sel = blockIdx.y;
    const float* W    = sel ? Wr : Wl;
    const float* bvec = sel ? br : bl;
    int t = threadIdx.x;
    int nb = blockIdx.x * 32;
    if (t < 32) xs[t] = (nb + t < NN) ? x[nb + t] : 0;
    for (int i = t; i < EMBD * C1 / 4; i += 256)
        ((float4*)s_w)[i] = ((const float4*)W)[i];
    for (int i = t; i < (EMBP - EMBD) * C1 / 4; i += 256)
        ((float4*)s_w)[EMBD * C1 / 4 + i] = make_float4(0.f, 0.f, 0.f, 0.f);
    __syncthreads();
    for (int i = t; i < 32 * EMBP; i += 256) {
        int n = i / EMBP, k = i % EMBP;
        float v = (k < EMBD) ? emb[(size_t)xs[n] * EMBD + k] : 0.f;
        s_h2[i * 2] = v; s_h2[i * 2 + 1] = v;
    }
    __syncthreads();
    int cg = t & 63, g = t >> 6;
    int c0 = cg * 4;
    float4 bv = *(const float4*)&bvec[c0];
    ulonglong2 acc[8];
#pragma unroll
    for (int j = 0; j < 8; j++) {
        acc[j].x = pack2(bv.x, bv.y);
        acc[j].y = pack2(bv.z, bv.w);
    }
#pragma unroll 4
    for (int k = 0; k < EMBP; k++) {
        ulonglong2 w = *(const ulonglong2*)&s_w[k * C1 + c0];
#pragma unroll
        for (int j = 0; j < 8; j++) {
            unsigned long long h2 =
                *(const unsigned long long*)&s_h2[((g * 8 + j) * EMBP + k) * 2];
            acc[j].x = fma2(h2, w.x, acc[j].x);
            acc[j].y = fma2(h2, w.y, acc[j].y);
        }
    }
    float* dst = sel ? g_xr : g_xl;
#pragma unroll
    for (int j = 0; j < 8; j++) {
        int n = nb + g * 8 + j;
        if (n < NN) {
            float2 lo = unpack2(acc[j].x), hi = unpack2(acc[j].y);
            *(float4*)&dst[(size_t)n * C1 + c0] = make_float4(lo.x, lo.y, hi.x, hi.y);
        }
    }
}

// edge logits L1, CSR order: writes exp(logit) and accumulates denominator
__global__ __launch_bounds__(256, 4) void k_edge1(const float* __restrict__ ea,
                                                  const float* __restrict__ We,
                                                  const float* __restrict__ att) {
    extern __shared__ float sm[];
    float* s_we  = sm;                      // 28*256 = 7168 floats
    float* s_ea2 = sm + 7168;               // 32*28*2 = 1792 floats
    __shared__ int s_src[TE], s_dst[TE], s_eid[TE];
    int t  = threadIdx.x;
    int eb = blockIdx.x * TE;
    if (t < TE) {
        s_src[t] = g_esrc[eb + t];
        s_dst[t] = g_edst[eb + t];
        s_eid[t] = g_eid[eb + t];
    }
    for (int i = t; i < ED * C1 / 4; i += 256)
        ((float4*)s_we)[i] = ((const float4*)We)[i];
    __syncthreads();
    for (int i = t; i < TE * ED; i += 256) {
        int e = i / ED, k = i - e * ED;
        float v = ea[(size_t)s_eid[e] * ED + k];
        s_ea2[i * 2] = v; s_ea2[i * 2 + 1] = v;
    }
    int cg = t & 63, eq = t >> 6;
    int c0 = cg * 4;
    ulonglong2 acc[8];
#pragma unroll
    for (int j = 0; j < 8; j++) {
        int e = eq * 8 + j;
        float4 a = *(const float4*)&g_xl[(size_t)s_src[e] * C1 + c0];
        float4 b = *(const float4*)&g_xr[(size_t)s_dst[e] * C1 + c0];
        acc[j].x = pack2(a.x + b.x, a.y + b.y);
        acc[j].y = pack2(a.z + b.z, a.w + b.w);
    }
    __syncthreads();
#pragma unroll 4
    for (int k = 0; k < ED; k++) {
        ulonglong2 w = *(const ulonglong2*)&s_we[k * C1 + c0];
#pragma unroll
        for (int j = 0; j < 8; j++) {
            unsigned long long e2 =
                *(const unsigned long long*)&s_ea2[((eq * 8 + j) * ED + k) * 2];
            acc[j].x = fma2(e2, w.x, acc[j].x);
            acc[j].y = fma2(e2, w.y, acc[j].y);
        }
    }
    float a0 = att[c0], a1 = att[c0 + 1], a2 = att[c0 + 2], a3 = att[c0 + 3];
    float part[8];
#pragma unroll
    for (int j = 0; j < 8; j++) {
        float2 lo = unpack2(acc[j].x), hi = unpack2(acc[j].y);
        part[j] = lrelu(lo.x) * a0 + lrelu(lo.y) * a1 +
                  lrelu(hi.x) * a2 + lrelu(hi.y) * a3;
    }
#pragma unroll
    for (int off = 8; off; off >>= 1) {
#pragma unroll
        for (int j = 0; j < 8; j++)
            part[j] += __shfl_down_sync(0xffffffffu, part[j], off);
    }
    int lane = t & 31;
    if ((lane & 15) == 0) {
        int h = cg >> 4;
#pragma unroll
        for (int j = 0; j < 8; j++) {
            int e = eq * 8 + j;
            float ex = expf(part[j]);
            g_logit[(size_t)(eb + e) * 4 + h] = ex;     // alpha numerator, CSR order
            atomicAdd(&g_den[s_dst[e] * 4 + h], ex);
        }
    }
}

// aggregation L1: pure weighted gather (alpha precomputed) + fused LN stats
__global__ __launch_bounds__(256) void k_agg1(const float* __restrict__ bias) {
    int t = threadIdx.x;
    int n = blockIdx.x * 4 + (t >> 6);
    int t64 = t & 63;
    int lane = t & 31;
    int c0 = t64 * 4;
    int h  = t64 >> 4;
    int s = g_off[n], en = g_off[n + 1];
    float4 acc = make_float4(0.f, 0.f, 0.f, 0.f);
    for (int p = s; p < en; p++) {
        float ex = g_logit[(size_t)p * 4 + h];
        int src = g_esrc[p];
        float4 v = *(const float4*)&g_xl[(size_t)src * C1 + c0];
        acc.x += ex * v.x; acc.y += ex * v.y;
        acc.z += ex * v.z; acc.w += ex * v.w;
    }
    float inv = 1.f / (g_den[n * 4 + h] + 1e-16f);
    float4 bv = *(const float4*)&bias[c0];
    float4 o;
    o.x = acc.x * inv + bv.x; o.y = acc.y * inv + bv.y;
    o.z = acc.z * inv + bv.z; o.w = acc.w * inv + bv.w;
    *(float4*)&g_h1[(size_t)n * C1 + c0] = o;
    float sv = o.x + o.y + o.z + o.w;
    float qv = o.x * o.x + o.y * o.y + o.z * o.z + o.w * o.w;
#pragma unroll
    for (int off = 16; off; off >>= 1) {
        sv += __shfl_down_sync(0xffffffffu, sv, off);
        qv += __shfl_down_sync(0xffffffffu, qv, off);
    }
    __shared__ double sh[8], qh[8];
    int w = t >> 5;
    if (lane == 0) { sh[w] = (double)sv; qh[w] = (double)qv; }
    __syncthreads();
    if (t == 0) {
        double S = 0.0, Q = 0.0;
        for (int i = 0; i < 8; i++) { S += sh[i]; Q += qh[i]; }
        atomicAdd(&g_red[0], S); atomicAdd(&g_red[1], Q);
    }
}

// node transform L2: fused LN1+ReLU, duplicated-h smem, f32x2
__global__ __launch_bounds__(256) void k_node2(const float* __restrict__ Wl,
                                               const float* __restrict__ bl,
                                               const float* __restrict__ Wr,
                                               const float* __restrict__ br,
                                               const float* __restrict__ lnw,
                                               const float* __restrict__ lnb) {
    __shared__ float hs2[16 * C1 * 2];
    __shared__ float s_lnw[C1], s_lnb[C1];
    __shared__ float s_mf[2];
    int t = threadIdx.x;
    int nb = blockIdx.x * 16;
    if (t < C1) { s_lnw[t] = lnw[t]; s_lnb[t] = lnb[t]; }
    if (t == 0) {
        double M = (double)NN * C1;
        double mean = g_red[0] / M;
        double var  = g_red[1] / M - mean * mean;
        s_mf[0] = (float)mean;
        s_mf[1] = 1.f / ((float)sqrt(var > 0.0 ? var : 0.0) + 1e-5f);
    }
    __syncthreads();
    float mean = s_mf[0], f = s_mf[1];
    for (int i = t; i < 16 * C1 / 4; i += 256) {
        float4 v = *(const float4*)&g_h1[(size_t)nb * C1 + (size_t)i * 4];
        int k = (i & 63) * 4;
        float4 w4 = *(const float4*)&s_lnw[k];
        float4 b4 = *(const float4*)&s_lnb[k];
        v.x = (v.x - mean) * f * w4.x + b4.x; v.x = v.x > 0.f ? v.x : 0.f;
        v.y = (v.y - mean) * f * w4.y + b4.y; v.y = v.y > 0.f ? v.y : 0.f;
        v.z = (v.z - mean) * f * w4.z + b4.z; v.z = v.z > 0.f ? v.z : 0.f;
        v.w = (v.w - mean) * f * w4.w + b4.w; v.w = v.w > 0.f ? v.w : 0.f;
        *(float4*)&hs2[i * 8]     = make_float4(v.x, v.x, v.y, v.y);
        *(float4*)&hs2[i * 8 + 4] = make_float4(v.z, v.z, v.w, v.w);
    }
    __syncthreads();
    int cp = t & 31;
    int c2 = cp * 2;
    int grp = t >> 5;
    int n0 = grp * 2, n1 = grp * 2 + 1;
    bool act = (c2 + 1) < C2;
    unsigned long long blv = 0, brv = 0;
    if (act) {
        blv = pack2(bl[c2], bl[c2 + 1]);
        brv = pack2(br[c2], br[c2 + 1]);
    }
    unsigned long long al0 = blv, al1 = blv, ar0 = brv, ar1 = brv;
#pragma unroll 4
    for (int k = 0; k < C1; k++) {
        unsigned long long wl = 0, wr = 0;
        if (act) {
            wl = *(const unsigned long long*)&Wl[k * C2 + c2];
            wr = *(const unsigned long long*)&Wr[k * C2 + c2];
        }
        unsigned long long h0 = *(const unsigned long long*)&hs2[(n0 * C1 + k) * 2];
        unsigned long long h1 = *(const unsigned long long*)&hs2[(n1 * C1 + k) * 2];
        al0 = fma2(h0, wl, al0);
        al1 = fma2(h1, wl, al1);
        ar0 = fma2(h0, wr, ar0);
        ar1 = fma2(h1, wr, ar1);
    }
    if (act) {
        float2 v;
        v = unpack2(al0); *(float2*)&g_xl[(size_t)(nb + n0) * C2 + c2] = v;
        v = unpack2(al1); *(float2*)&g_xl[(size_t)(nb + n1) * C2 + c2] = v;
        v = unpack2(ar0); *(float2*)&g_xr[(size_t)(nb + n0) * C2 + c2] = v;
        v = unpack2(ar1); *(float2*)&g_xr[(size_t)(nb + n1) * C2 + c2] = v;
    }
}

// edge logits L2, CSR order: block-tile, smem ea splats (no shfl chain), f32x2
__global__ __launch_bounds__(256, 4) void k_edge2(const float* __restrict__ ea,
                                                  const float* __restrict__ We,
                                                  const float* __restrict__ att) {
    __shared__ float s_we2[ED * 64];          // zero-padded 50->64 cols
    __shared__ float s_ea2[TE2 * ED * 2];     // duplicated splats
    __shared__ float s_att[64];
    __shared__ int s_src[TE2], s_dst[TE2], s_eid[TE2];
    int t = threadIdx.x;
    int eb = blockIdx.x * TE2;
    if (t < TE2) {
        s_src[t] = g_esrc[eb + t];
        s_dst[t] = g_edst[eb + t];
        s_eid[t] = g_eid[eb + t];
    }
    if (t < 64) s_att[t] = (t < C2) ? att[t] : 0.f;
    for (int i = t; i < ED * 64; i += 256) {
        int k = i >> 6, c = i & 63;
        s_we2[i] = (c < C2) ? We[k * C2 + c] : 0.f;
    }
    __syncthreads();                           // s_eid ready
    for (int i = t; i < TE2 * ED; i += 256) {
        int e = i / ED, k = i - e * ED;
        float v = ea[(size_t)s_eid[e] * ED + k];
        s_ea2[i * 2] = v; s_ea2[i * 2 + 1] = v;
    }
    int cg = t & 31, eq = t >> 5;              // warp = 4 edges, lane = col pair
    int c0 = cg * 2;
    bool act = c0 < C2;
    unsigned long long acc[4];
#pragma unroll
    for (int j = 0; j < 4; j++) {
        int e = eq * 4 + j;
        float mx = 0.f, my = 0.f;
        if (act) {
            float2 u = *(const float2*)&g_xl[(size_t)s_src[e] * C2 + c0];
            float2 v = *(const float2*)&g_xr[(size_t)s_dst[e] * C2 + c0];
            mx = u.x + v.x; my = u.y + v.y;
        }
        acc[j] = pack2(mx, my);
    }
    __syncthreads();                           // s_ea2 / s_we2 ready
#pragma unroll 4
    for (int k = 0; k < ED; k++) {
        unsigned long long w2 = *(const unsigned long long*)&s_we2[k * 64 + c0];
#pragma unroll
        for (int j = 0; j < 4; j++) {
            unsigned long long e2 =
                *(const unsigned long long*)&s_ea2[((eq * 4 + j) * ED + k) * 2];
            acc[j] = fma2(e2, w2, acc[j]);
        }
    }
    float2 a2 = *(const float2*)&s_att[c0];    // zero for inactive lanes
    float part[4];
#pragma unroll
    for (int j = 0; j < 4; j++) {
        float2 m = unpack2(acc[j]);
        part[j] = lrelu(m.x) * a2.x + lrelu(m.y) * a2.y;
    }
#pragma unroll
    for (int off = 16; off; off >>= 1) {
#pragma unroll
        for (int j = 0; j < 4; j++)
            part[j] += __shfl_down_sync(0xffffffffu, part[j], off);
    }
    if (cg == 0) {
#pragma unroll
        for (int j = 0; j < 4; j++) {
            int e = eq * 4 + j;
            float ex = expf(part[j]);
            g_logit[eb + e] = ex;              // alpha numerator, CSR order
            atomicAdd(&g_den[4 * NN + s_dst[e]], ex);
        }
    }
}

// aggregation L2: pure weighted gather + fused LN stats
__global__ __launch_bounds__(256) void k_agg2(const float* __restrict__ bias) {
    int t = threadIdx.x;
    int n = blockIdx.x * 4 + (t >> 6);
    int t64 = t & 63;
    int lane = t & 31;
    int s = g_off[n], en = g_off[n + 1];
    bool act = t64 < C2;
    float acc = 0.f;
    for (int p = s; p < en; p++) {
        float ex = g_logit[p];
        int src = g_esrc[p];
        if (act) acc += ex * g_xl[(size_t)src * C2 + t64];
    }
    float o = 0.f;
    if (act) {
        o = acc / (g_den[4 * NN + n] + 1e-16f) + bias[t64];
        g_o2[(size_t)n * C2 + t64] = o;
    }
    float sv = o, qv = o * o;
#pragma unroll
    for (int off = 16; off; off >>= 1) {
        sv += __shfl_down_sync(0xffffffffu, sv, off);
        qv += __shfl_down_sync(0xffffffffu, qv, off);
    }
    __shared__ double sh[8], qh[8];
    int w = t >> 5;
    if (lane == 0) { sh[w] = (double)sv; qh[w] = (double)qv; }
    __syncthreads();
    if (t == 0) {
        double S = 0.0, Q = 0.0;
        for (int i = 0; i < 8; i++) { S += sh[i]; Q += qh[i]; }
        atomicAdd(&g_red[2], S); atomicAdd(&g_red[3], Q);
    }
}

__global__ void k_ln2(float* __restrict__ out, const float* __restrict__ w,
                      const float* __restrict__ b) {
    int i = blockIdx.x * blockDim.x + threadIdx.x;
    if (i < NN * C2) {
        double M = (double)NN * C2;
        double mean = g_red[2] / M;
        double var  = g_red[3] / M - mean * mean;
        float f = 1.f / ((float)sqrt(var > 0.0 ? var : 0.0) + 1e-5f);
        int c = i % C2;
        out[i] = (g_o2[i] - (float)mean) * f * w[c] + b[c];
    }
}

extern "C" void kernel_launch(void* const* d_in, const int* in_sizes, int n_in,
                              void* d_out, int out_size) {
    const int*   x    = (const int*)d_in[0];
    const int*   ei   = (const int*)d_in[1];
    const float* ea   = (const float*)d_in[2];
    const float* emb  = (const float*)d_in[3];
    const float* Wl1  = (const float*)d_in[4];
    const float* bl1  = (const float*)d_in[5];
    const float* Wr1  = (const float*)d_in[6];
    const float* br1  = (const float*)d_in[7];
    const float* We1  = (const float*)d_in[8];
    const float* att1 = (const float*)d_in[9];
    const float* bias1= (const float*)d_in[10];
    const float* ln1w = (const float*)d_in[11];
    const float* ln1b = (const float*)d_in[12];
    const float* Wl2  = (const float*)d_in[13];
    const float* bl2  = (const float*)d_in[14];
    const float* Wr2  = (const float*)d_in[15];
    const float* br2  = (const float*)d_in[16];
    const float* We2  = (const float*)d_in[17];
    const float* att2 = (const float*)d_in[18];
    const float* bias2= (const float*)d_in[19];
    const float* ln2w = (const float*)d_in[20];
    const float* ln2b = (const float*)d_in[21];
    float* out = (float*)d_out;

    const int node1_smem = (EMBP * C1 + 32 * EMBP * 2) * 4;   // ~66.6 KB
    const int edge1_smem = (7168 + TE * ED * 2) * 4;          // ~35.8 KB
    const int scan_smem  = NN * 4;                            // 200 KB
    cudaFuncSetAttribute(k_node1, cudaFuncAttributeMaxDynamicSharedMemorySize, node1_smem);
    cudaFuncSetAttribute(k_edge1, cudaFuncAttributeMaxDynamicSharedMemorySize, edge1_smem);
    cudaFuncSetAttribute(k_scan,  cudaFuncAttributeMaxDynamicSharedMemorySize, scan_smem);

    dim3 n1grid((NN + 31) / 32, 2);

    k_init<<<(5 * NN + 255) / 256, 256>>>();                               // 1
    k_deg<<<(EE + 255) / 256, 256>>>(ei);                                  // 2
    k_scan<<<1, 1024, scan_smem>>>();                                      // 3
    k_node1<<<n1grid, 256, node1_smem>>>(x, emb, Wl1, bl1, Wr1, br1);      // 4
    k_fill<<<(EE + 255) / 256, 256>>>(ei);                                 // 5
    k_edge1<<<EE / TE, 256, edge1_smem>>>(ea, We1, att1);                  // 6
    k_agg1<<<NN / 4, 256>>>(bias1);                                        // 7
    k_node2<<<NN / 16, 256>>>(Wl2, bl2, Wr2, br2, ln1w, ln1b);             // 8
    k_edge2<<<EE / TE2, 256>>>(ea, We2, att2);                             // 9
    k_agg2<<<NN / 4, 256>>>(bias2);                                        // 10
    k_ln2<<<(NN * C2 + 255) / 256, 256>>>(out, ln2w, ln2b);                // 11
}